// round 12
// baseline (speedup 1.0000x reference)
#include <cuda_runtime.h>
#include <cuda_bf16.h>
#include <cstdint>

static constexpr int D = 128;       // feature dim == hidden dim
static constexpr int MAXN = 100000;

// accumulator: ZERO at every kernel_launch entry (module-load zero-init +
// the MLP restores zeros after consuming). Scatter red.v4's into it.
__device__ __align__(128) float g_acc[(size_t)MAXN * D];
// pre-split, transposed bf16 weights: [n][k] row-major, 128x128 each
__device__ __align__(16) __nv_bfloat16 g_w1hi[16384];
__device__ __align__(16) __nv_bfloat16 g_w1lo[16384];
__device__ __align__(16) __nv_bfloat16 g_w2hi[16384];
__device__ __align__(16) __nv_bfloat16 g_w2lo[16384];

// ---------------------------------------------------------------------------
// helpers
// ---------------------------------------------------------------------------
__device__ __forceinline__ uint32_t smem_to_u32(const void* p) {
    uint32_t a;
    asm("{ .reg .u64 t; cvta.to.shared.u64 t, %1; cvt.u32.u64 %0, t; }"
        : "=r"(a) : "l"(p));
    return a;
}
__device__ __forceinline__ void ldsm4(uint32_t r[4], uint32_t addr) {
    asm volatile("ldmatrix.sync.aligned.m8n8.x4.shared.b16 {%0,%1,%2,%3}, [%4];"
                 : "=r"(r[0]), "=r"(r[1]), "=r"(r[2]), "=r"(r[3]) : "r"(addr));
}
__device__ __forceinline__ void mma16816(float c[4], const uint32_t a[4],
                                         uint32_t b0, uint32_t b1) {
    asm volatile("mma.sync.aligned.m16n8k16.row.col.f32.bf16.bf16.f32 "
                 "{%0,%1,%2,%3}, {%4,%5,%6,%7}, {%8,%9}, {%0,%1,%2,%3};"
                 : "+f"(c[0]), "+f"(c[1]), "+f"(c[2]), "+f"(c[3])
                 : "r"(a[0]), "r"(a[1]), "r"(a[2]), "r"(a[3]),
                   "r"(b0), "r"(b1));
}
__device__ __forceinline__ void split2(float v0, float v1,
                                       uint32_t& hp, uint32_t& lp) {
    __nv_bfloat16 h0 = __float2bfloat16(v0);
    __nv_bfloat16 h1 = __float2bfloat16(v1);
    __nv_bfloat16 l0 = __float2bfloat16(v0 - __bfloat162float(h0));
    __nv_bfloat16 l1 = __float2bfloat16(v1 - __bfloat162float(h1));
    hp = (uint32_t)__bfloat16_as_ushort(h0) |
         ((uint32_t)__bfloat16_as_ushort(h1) << 16);
    lp = (uint32_t)__bfloat16_as_ushort(l0) |
         ((uint32_t)__bfloat16_as_ushort(l1) << 16);
}
// x row load pinned in L2 via cache-hint policy (evict_last) — R8-proven
__device__ __forceinline__ float4 ldg_keep(const float4* p, uint64_t pol) {
    float4 v;
    asm volatile("ld.global.nc.L2::cache_hint.v4.f32 {%0,%1,%2,%3}, [%4], %5;"
                 : "=f"(v.x), "=f"(v.y), "=f"(v.z), "=f"(v.w)
                 : "l"(p), "l"(pol));
    return v;
}

// ---------------------------------------------------------------------------
// weight prep only (acc needs no init: zero-restoring invariant)
// ---------------------------------------------------------------------------
__global__ void prep_kernel(const float* __restrict__ W1,
                            const float* __restrict__ W2) {
    int idx = blockIdx.x * 256 + threadIdx.x;   // 0..32767
    int m = idx >> 14;
    int r = idx & 16383;
    int k = r >> 7, n = r & 127;
    float w = (m ? W2 : W1)[k * 128 + n];
    __nv_bfloat16 h = __float2bfloat16(w);
    __nv_bfloat16 l = __float2bfloat16(w - __bfloat162float(h));
    int e = n * 128 + k;
    if (m) { g_w2hi[e] = h; g_w2lo[e] = l; }
    else   { g_w1hi[e] = h; g_w1lo[e] = l; }
}

// ---------------------------------------------------------------------------
// scatter (exact R8 form, proven): one warp per edge, red.v4 into g_acc;
// x pinned evict_last, ea streamed evict-first
// ---------------------------------------------------------------------------
__global__ void scatter_kernel(const float* __restrict__ x,
                               const float* __restrict__ ea,
                               const int* __restrict__ ei, int E) {
    int gtid = blockIdx.x * blockDim.x + threadIdx.x;
    int e = gtid >> 5;
    int lane = gtid & 31;
    if (e >= E) return;

    uint64_t pol;
    asm volatile("createpolicy.fractional.L2::evict_last.b64 %0, 1.0;"
                 : "=l"(pol));

    int u = ei[e];
    int v = ei[E + e];

    float4 a  = __ldcs(reinterpret_cast<const float4*>(ea + (size_t)e * D) + lane);
    float4 xu = ldg_keep(reinterpret_cast<const float4*>(x + (size_t)u * D) + lane, pol);
    float4 xv = ldg_keep(reinterpret_cast<const float4*>(x + (size_t)v * D) + lane, pol);

    float4 mu, mv;
    mu.x = fmaxf(xv.x + a.x, 0.0f); mu.y = fmaxf(xv.y + a.y, 0.0f);
    mu.z = fmaxf(xv.z + a.z, 0.0f); mu.w = fmaxf(xv.w + a.w, 0.0f);
    mv.x = fmaxf(xu.x + a.x, 0.0f); mv.y = fmaxf(xu.y + a.y, 0.0f);
    mv.z = fmaxf(xu.z + a.z, 0.0f); mv.w = fmaxf(xu.w + a.w, 0.0f);

    float* pu = g_acc + (size_t)u * D + lane * 4;
    float* pv = g_acc + (size_t)v * D + lane * 4;
    asm volatile("red.global.add.v4.f32 [%0], {%1,%2,%3,%4};"
                 :: "l"(pu), "f"(mu.x), "f"(mu.y), "f"(mu.z), "f"(mu.w) : "memory");
    asm volatile("red.global.add.v4.f32 [%0], {%1,%2,%3,%4};"
                 :: "l"(pv), "f"(mv.x), "f"(mv.y), "f"(mv.z), "f"(mv.w) : "memory");
}

// ---------------------------------------------------------------------------
// PERSISTENT fused MLP on HMMA (bf16 2-term split => ~fp32 accuracy)
// 512 threads / 16 warps per CTA; W1+W2 hi/lo staged in smem ONCE;
// grid-stride over 256-row tiles. A = acc + (1+eps)*x built in registers;
// after reading, each lane ZEROES its acc slices (restores the invariant).
// ---------------------------------------------------------------------------
static constexpr int RS = 136;                        // row stride (bf16)
static constexpr int WT = 128 * RS * 2;               // 34816 B per tile
static constexpr int SM_W1HI = 0;
static constexpr int SM_W1LO = SM_W1HI + WT;
static constexpr int SM_W2HI = SM_W1LO + WT;
static constexpr int SM_W2LO = SM_W2HI + WT;          // 139264
static constexpr int SM_B1   = SM_W2LO + WT;
static constexpr int SM_B2   = SM_B1 + 512;
static constexpr int SM_TOTAL = SM_B2 + 512;          // 140800 B

__device__ __forceinline__ void copy_w512(char* smem, int dst,
                                          const __nv_bfloat16* src, int tid) {
    const uint4* s = reinterpret_cast<const uint4*>(src);
    #pragma unroll
    for (int i = tid; i < 2048; i += 512) {
        int r = i >> 4, c8 = i & 15;
        *reinterpret_cast<uint4*>(smem + dst + (r * RS + c8 * 8) * 2) = s[i];
    }
}

__device__ __forceinline__ void load_split(const float* ap, const float* xp,
                                           bool valid, int k, float s,
                                           uint32_t& hp, uint32_t& lp) {
    float v0 = 0.f, v1 = 0.f;
    if (valid) {
        float2 pa = __ldcs(reinterpret_cast<const float2*>(ap + k));
        float2 px = *reinterpret_cast<const float2*>(xp + k);
        v0 = fmaf(s, px.x, pa.x);
        v1 = fmaf(s, px.y, pa.y);
    }
    split2(v0, v1, hp, lp);
}

__global__ void __launch_bounds__(512, 1)
mlp_kernel(const float* __restrict__ x, const float* __restrict__ eps,
           const float* __restrict__ b1, const float* __restrict__ b2,
           float* __restrict__ out, int N, int ntiles) {
    extern __shared__ char smem[];
    uint32_t sb = smem_to_u32(smem);
    int tid = threadIdx.x;
    int wid = tid >> 5;
    int lane = tid & 31;

    copy_w512(smem, SM_W1HI, g_w1hi, tid);
    copy_w512(smem, SM_W1LO, g_w1lo, tid);
    copy_w512(smem, SM_W2HI, g_w2hi, tid);
    copy_w512(smem, SM_W2LO, g_w2lo, tid);
    if (tid < 128) {
        reinterpret_cast<float*>(smem + SM_B1)[tid] = b1[tid];
        reinterpret_cast<float*>(smem + SM_B2)[tid] = b2[tid];
    }
    __syncthreads();     // only barrier in the kernel

    int m2 = (lane & 3) * 2;
    int g  = lane >> 2;
    int brow = (lane & 7) + ((lane & 16) ? 8 : 0);
    int bcol = (lane & 8) ? 8 : 0;
    const float* b1s = reinterpret_cast<const float*>(smem + SM_B1);
    const float* b2s = reinterpret_cast<const float*>(smem + SM_B2);
    float s = 1.0f + eps[0];

    for (int tile = blockIdx.x; tile < ntiles; tile += gridDim.x) {
        int row0 = tile * 256;
        int r0 = row0 + wid * 16 + g;
        int r1 = r0 + 8;
        bool val0 = r0 < N, val1 = r1 < N;
        float* a0p = g_acc + (size_t)r0 * D;
        float* a1p = g_acc + (size_t)r1 * D;
        const float* x0p = x + (size_t)r0 * D;
        const float* x1p = x + (size_t)r1 * D;

        float c1[16][4];
        #pragma unroll
        for (int i = 0; i < 16; i++)
            c1[i][0] = c1[i][1] = c1[i][2] = c1[i][3] = 0.f;

        // ---- layer 1: A = acc + s*x from gmem, W1 from smem ----
        #pragma unroll 2
        for (int kk = 0; kk < 8; kk++) {
            int k0 = kk * 16 + m2;
            uint32_t ahi[4], alo[4];
            load_split(a0p, x0p, val0, k0,     s, ahi[0], alo[0]);
            load_split(a1p, x1p, val1, k0,     s, ahi[1], alo[1]);
            load_split(a0p, x0p, val0, k0 + 8, s, ahi[2], alo[2]);
            load_split(a1p, x1p, val1, k0 + 8, s, ahi[3], alo[3]);
            #pragma unroll
            for (int nt2 = 0; nt2 < 8; nt2++) {
                uint32_t bAddr = sb + SM_W1HI +
                    (uint32_t)((nt2 * 16 + brow) * RS + kk * 16 + bcol) * 2;
                uint32_t bhi[4], blo[4];
                ldsm4(bhi, bAddr);
                ldsm4(blo, bAddr + WT);
                mma16816(c1[2 * nt2],     ahi, bhi[0], bhi[1]);
                mma16816(c1[2 * nt2],     ahi, blo[0], blo[1]);
                mma16816(c1[2 * nt2],     alo, bhi[0], bhi[1]);
                mma16816(c1[2 * nt2 + 1], ahi, bhi[2], bhi[3]);
                mma16816(c1[2 * nt2 + 1], ahi, blo[2], blo[3]);
                mma16816(c1[2 * nt2 + 1], alo, bhi[2], bhi[3]);
            }
        }

        // ---- restore the zero invariant on the acc slices just consumed ----
        {
            float2 z = make_float2(0.f, 0.f);
            #pragma unroll
            for (int kk = 0; kk < 8; kk++) {
                int k0 = kk * 16 + m2;
                if (val0) {
                    *reinterpret_cast<float2*>(a0p + k0)     = z;
                    *reinterpret_cast<float2*>(a0p + k0 + 8) = z;
                }
                if (val1) {
                    *reinterpret_cast<float2*>(a1p + k0)     = z;
                    *reinterpret_cast<float2*>(a1p + k0 + 8) = z;
                }
            }
        }

        // ---- hidden = relu(c1 + b1), re-fragmented in registers ----
        uint32_t hh[8][4], hl[8][4];
        #pragma unroll
        for (int j = 0; j < 8; j++) {
            float be0 = b1s[16 * j + m2],     be1 = b1s[16 * j + m2 + 1];
            float bo0 = b1s[16 * j + 8 + m2], bo1 = b1s[16 * j + 8 + m2 + 1];
            split2(fmaxf(c1[2 * j][0] + be0, 0.f),
                   fmaxf(c1[2 * j][1] + be1, 0.f), hh[j][0], hl[j][0]);
            split2(fmaxf(c1[2 * j][2] + be0, 0.f),
                   fmaxf(c1[2 * j][3] + be1, 0.f), hh[j][1], hl[j][1]);
            split2(fmaxf(c1[2 * j + 1][0] + bo0, 0.f),
                   fmaxf(c1[2 * j + 1][1] + bo1, 0.f), hh[j][2], hl[j][2]);
            split2(fmaxf(c1[2 * j + 1][2] + bo0, 0.f),
                   fmaxf(c1[2 * j + 1][3] + bo1, 0.f), hh[j][3], hl[j][3]);
        }

        // ---- layer 2 in two n-halves (c2 = 32 regs), W2 from smem ----
        #pragma unroll
        for (int h = 0; h < 2; h++) {
            float c2[8][4];
            #pragma unroll
            for (int i = 0; i < 8; i++)
                c2[i][0] = c2[i][1] = c2[i][2] = c2[i][3] = 0.f;

            #pragma unroll
            for (int kk = 0; kk < 8; kk++) {
                #pragma unroll
                for (int i = 0; i < 4; i++) {
                    int nt2 = h * 4 + i;
                    uint32_t bAddr = sb + SM_W2HI +
                        (uint32_t)((nt2 * 16 + brow) * RS + kk * 16 + bcol) * 2;
                    uint32_t bhi[4], blo[4];
                    ldsm4(bhi, bAddr);
                    ldsm4(blo, bAddr + WT);
                    mma16816(c2[2 * i],     hh[kk], bhi[0], bhi[1]);
                    mma16816(c2[2 * i],     hh[kk], blo[0], blo[1]);
                    mma16816(c2[2 * i],     hl[kk], bhi[0], bhi[1]);
                    mma16816(c2[2 * i + 1], hh[kk], bhi[2], bhi[3]);
                    mma16816(c2[2 * i + 1], hh[kk], blo[2], blo[3]);
                    mma16816(c2[2 * i + 1], hl[kk], bhi[2], bhi[3]);
                }
            }

            #pragma unroll
            for (int nt = 0; nt < 8; nt++) {
                int col = (h * 8 + nt) * 8 + m2;
                float bb0 = b2s[col], bb1 = b2s[col + 1];
                if (val0)
                    *reinterpret_cast<float2*>(out + (size_t)r0 * D + col) =
                        make_float2(c2[nt][0] + bb0, c2[nt][1] + bb1);
                if (val1)
                    *reinterpret_cast<float2*>(out + (size_t)r1 * D + col) =
                        make_float2(c2[nt][2] + bb0, c2[nt][3] + bb1);
            }
        }
    }
}

// ---------------------------------------------------------------------------
// launch: scatter (acc==0 invariant) -> weight prep -> persistent HMMA MLP
// ---------------------------------------------------------------------------
extern "C" void kernel_launch(void* const* d_in, const int* in_sizes, int n_in,
                              void* d_out, int out_size) {
    const float* x   = (const float*)d_in[0];
    const float* ea  = (const float*)d_in[1];
    const float* W1  = (const float*)d_in[2];
    const float* b1  = (const float*)d_in[3];
    const float* W2  = (const float*)d_in[4];
    const float* b2  = (const float*)d_in[5];
    const float* eps = (const float*)d_in[6];
    const int*   ei  = (const int*)d_in[7];

    int N = in_sizes[0] / D;
    int E = in_sizes[1] / D;

    long long scatter_threads = (long long)E * 32;
    scatter_kernel<<<(int)((scatter_threads + 255) / 256), 256>>>(x, ea, ei, E);

    prep_kernel<<<128, 256>>>(W1, W2);

    cudaFuncSetAttribute(mlp_kernel,
                         cudaFuncAttributeMaxDynamicSharedMemorySize, SM_TOTAL);
    int ntiles = (N + 255) / 256;
    int grid = ntiles < 152 ? ntiles : 152;
    mlp_kernel<<<grid, 512, SM_TOTAL>>>(x, eps, b1, b2, (float*)d_out, N, ntiles);
}

// round 13
// speedup vs baseline: 1.0167x; 1.0167x over previous
#include <cuda_runtime.h>
#include <cuda_bf16.h>
#include <cstdint>

static constexpr int D = 128;       // feature dim == hidden dim
static constexpr int MAXN = 100000;

// accumulator: initialized to (1+eps)*x by setup, then scatter adds messages
__device__ __align__(128) float g_acc[(size_t)MAXN * D];
// pre-split, transposed bf16 weights: [n][k] row-major, 128x128 each
__device__ __align__(16) __nv_bfloat16 g_w1hi[16384];
__device__ __align__(16) __nv_bfloat16 g_w1lo[16384];
__device__ __align__(16) __nv_bfloat16 g_w2hi[16384];
__device__ __align__(16) __nv_bfloat16 g_w2lo[16384];

// ---------------------------------------------------------------------------
// helpers
// ---------------------------------------------------------------------------
__device__ __forceinline__ uint32_t smem_to_u32(const void* p) {
    uint32_t a;
    asm("{ .reg .u64 t; cvta.to.shared.u64 t, %1; cvt.u32.u64 %0, t; }"
        : "=r"(a) : "l"(p));
    return a;
}
__device__ __forceinline__ void ldsm4(uint32_t r[4], uint32_t addr) {
    asm volatile("ldmatrix.sync.aligned.m8n8.x4.shared.b16 {%0,%1,%2,%3}, [%4];"
                 : "=r"(r[0]), "=r"(r[1]), "=r"(r[2]), "=r"(r[3]) : "r"(addr));
}
__device__ __forceinline__ void mma16816(float c[4], const uint32_t a[4],
                                         uint32_t b0, uint32_t b1) {
    asm volatile("mma.sync.aligned.m16n8k16.row.col.f32.bf16.bf16.f32 "
                 "{%0,%1,%2,%3}, {%4,%5,%6,%7}, {%8,%9}, {%0,%1,%2,%3};"
                 : "+f"(c[0]), "+f"(c[1]), "+f"(c[2]), "+f"(c[3])
                 : "r"(a[0]), "r"(a[1]), "r"(a[2]), "r"(a[3]),
                   "r"(b0), "r"(b1));
}
__device__ __forceinline__ void split2(float v0, float v1,
                                       uint32_t& hp, uint32_t& lp) {
    __nv_bfloat16 h0 = __float2bfloat16(v0);
    __nv_bfloat16 h1 = __float2bfloat16(v1);
    __nv_bfloat16 l0 = __float2bfloat16(v0 - __bfloat162float(h0));
    __nv_bfloat16 l1 = __float2bfloat16(v1 - __bfloat162float(h1));
    hp = (uint32_t)__bfloat16_as_ushort(h0) |
         ((uint32_t)__bfloat16_as_ushort(h1) << 16);
    lp = (uint32_t)__bfloat16_as_ushort(l0) |
         ((uint32_t)__bfloat16_as_ushort(l1) << 16);
}
// x row load pinned in L2 via cache-hint policy (evict_last) — R8-proven
__device__ __forceinline__ float4 ldg_keep(const float4* p, uint64_t pol) {
    float4 v;
    asm volatile("ld.global.nc.L2::cache_hint.v4.f32 {%0,%1,%2,%3}, [%4], %5;"
                 : "=f"(v.x), "=f"(v.y), "=f"(v.z), "=f"(v.w)
                 : "l"(p), "l"(pol));
    return v;
}
// 128-bit vector reduction, destination pinned evict_last (anti-thrash)
__device__ __forceinline__ void red_v4_keep(float* p, float m0, float m1,
                                            float m2, float m3, uint64_t pol) {
    asm volatile("red.global.add.L2::cache_hint.v4.f32 [%0], {%1,%2,%3,%4}, %5;"
                 :: "l"(p), "f"(m0), "f"(m1), "f"(m2), "f"(m3), "l"(pol)
                 : "memory");
}

// ---------------------------------------------------------------------------
// setup: blocks [0,128) split weights; blocks [128,...) acc = (1+eps)*x
// ---------------------------------------------------------------------------
__global__ void setup_kernel(const float* __restrict__ W1,
                             const float* __restrict__ W2,
                             const float* __restrict__ x,
                             const float* __restrict__ eps, int ninit4) {
    int b = blockIdx.x, t = threadIdx.x;
    if (b < 128) {
        int idx = b * 256 + t;           // 0..32767
        int m = idx >> 14;
        int r = idx & 16383;
        int k = r >> 7, n = r & 127;
        float w = (m ? W2 : W1)[k * 128 + n];
        __nv_bfloat16 h = __float2bfloat16(w);
        __nv_bfloat16 l = __float2bfloat16(w - __bfloat162float(h));
        int e = n * 128 + k;
        if (m) { g_w2hi[e] = h; g_w2lo[e] = l; }
        else   { g_w1hi[e] = h; g_w1lo[e] = l; }
    } else {
        int i = (b - 128) * 256 + t;
        if (i < ninit4) {
            float s = 1.0f + *eps;
            float4 v = reinterpret_cast<const float4*>(x)[i];
            v.x *= s; v.y *= s; v.z *= s; v.w *= s;
            reinterpret_cast<float4*>(g_acc)[i] = v;
        }
    }
}

// ---------------------------------------------------------------------------
// scatter: one warp per edge (R8 geometry), red.v4 into g_acc.
// x pinned evict_last; acc RMW ALSO pinned evict_last (isolated change);
// ea streamed evict-first via __ldcs.
// ---------------------------------------------------------------------------
__global__ void scatter_kernel(const float* __restrict__ x,
                               const float* __restrict__ ea,
                               const int* __restrict__ ei, int E) {
    int gtid = blockIdx.x * blockDim.x + threadIdx.x;
    int e = gtid >> 5;
    int lane = gtid & 31;
    if (e >= E) return;

    uint64_t pol;
    asm volatile("createpolicy.fractional.L2::evict_last.b64 %0, 1.0;"
                 : "=l"(pol));

    int u = ei[e];
    int v = ei[E + e];

    float4 a  = __ldcs(reinterpret_cast<const float4*>(ea + (size_t)e * D) + lane);
    float4 xu = ldg_keep(reinterpret_cast<const float4*>(x + (size_t)u * D) + lane, pol);
    float4 xv = ldg_keep(reinterpret_cast<const float4*>(x + (size_t)v * D) + lane, pol);

    float4 mu, mv;
    mu.x = fmaxf(xv.x + a.x, 0.0f); mu.y = fmaxf(xv.y + a.y, 0.0f);
    mu.z = fmaxf(xv.z + a.z, 0.0f); mu.w = fmaxf(xv.w + a.w, 0.0f);
    mv.x = fmaxf(xu.x + a.x, 0.0f); mv.y = fmaxf(xu.y + a.y, 0.0f);
    mv.z = fmaxf(xu.z + a.z, 0.0f); mv.w = fmaxf(xu.w + a.w, 0.0f);

    float* pu = g_acc + (size_t)u * D + lane * 4;
    float* pv = g_acc + (size_t)v * D + lane * 4;
    red_v4_keep(pu, mu.x, mu.y, mu.z, mu.w, pol);
    red_v4_keep(pv, mv.x, mv.y, mv.z, mv.w, pol);
}

// ---------------------------------------------------------------------------
// PERSISTENT fused MLP on HMMA (bf16 2-term split => ~fp32 accuracy)
// 512 threads / 16 warps per CTA; W1+W2 hi/lo staged in smem ONCE;
// grid-stride loop over 256-row tiles; NO syncs after the initial barrier.
// (exact R11 form, 204.9 us proven)
// ---------------------------------------------------------------------------
static constexpr int RS = 136;                        // row stride (bf16)
static constexpr int WT = 128 * RS * 2;               // 34816 B per tile
static constexpr int SM_W1HI = 0;
static constexpr int SM_W1LO = SM_W1HI + WT;
static constexpr int SM_W2HI = SM_W1LO + WT;
static constexpr int SM_W2LO = SM_W2HI + WT;          // 139264
static constexpr int SM_B1   = SM_W2LO + WT;
static constexpr int SM_B2   = SM_B1 + 512;
static constexpr int SM_TOTAL = SM_B2 + 512;          // 140800 B

__device__ __forceinline__ void copy_w512(char* smem, int dst,
                                          const __nv_bfloat16* src, int tid) {
    const uint4* s = reinterpret_cast<const uint4*>(src);
    #pragma unroll
    for (int i = tid; i < 2048; i += 512) {
        int r = i >> 4, c8 = i & 15;
        *reinterpret_cast<uint4*>(smem + dst + (r * RS + c8 * 8) * 2) = s[i];
    }
}

__device__ __forceinline__ void load_split(const float* ap, bool valid, int k,
                                           uint32_t& hp, uint32_t& lp) {
    float v0 = 0.f, v1 = 0.f;
    if (valid) {
        float2 p = *reinterpret_cast<const float2*>(ap + k);
        v0 = p.x; v1 = p.y;
    }
    split2(v0, v1, hp, lp);
}

__global__ void __launch_bounds__(512, 1)
mlp_kernel(const float* __restrict__ b1, const float* __restrict__ b2,
           float* __restrict__ out, int N, int ntiles) {
    extern __shared__ char smem[];
    uint32_t sb = smem_to_u32(smem);
    int tid = threadIdx.x;
    int wid = tid >> 5;
    int lane = tid & 31;

    copy_w512(smem, SM_W1HI, g_w1hi, tid);
    copy_w512(smem, SM_W1LO, g_w1lo, tid);
    copy_w512(smem, SM_W2HI, g_w2hi, tid);
    copy_w512(smem, SM_W2LO, g_w2lo, tid);
    if (tid < 128) {
        reinterpret_cast<float*>(smem + SM_B1)[tid] = b1[tid];
        reinterpret_cast<float*>(smem + SM_B2)[tid] = b2[tid];
    }
    __syncthreads();     // only barrier in the kernel

    int m2 = (lane & 3) * 2;
    int g  = lane >> 2;
    int brow = (lane & 7) + ((lane & 16) ? 8 : 0);
    int bcol = (lane & 8) ? 8 : 0;
    const float* b1s = reinterpret_cast<const float*>(smem + SM_B1);
    const float* b2s = reinterpret_cast<const float*>(smem + SM_B2);

    for (int tile = blockIdx.x; tile < ntiles; tile += gridDim.x) {
        int row0 = tile * 256;
        int r0 = row0 + wid * 16 + g;
        int r1 = r0 + 8;
        bool val0 = r0 < N, val1 = r1 < N;
        const float* a0p = g_acc + (size_t)r0 * D;
        const float* a1p = g_acc + (size_t)r1 * D;

        float c1[16][4];
        #pragma unroll
        for (int i = 0; i < 16; i++)
            c1[i][0] = c1[i][1] = c1[i][2] = c1[i][3] = 0.f;

        // ---- layer 1: A from gmem, W1 from smem ----
        #pragma unroll 2
        for (int kk = 0; kk < 8; kk++) {
            int k0 = kk * 16 + m2;
            uint32_t ahi[4], alo[4];
            load_split(a0p, val0, k0,     ahi[0], alo[0]);
            load_split(a1p, val1, k0,     ahi[1], alo[1]);
            load_split(a0p, val0, k0 + 8, ahi[2], alo[2]);
            load_split(a1p, val1, k0 + 8, ahi[3], alo[3]);
            #pragma unroll
            for (int nt2 = 0; nt2 < 8; nt2++) {
                uint32_t bAddr = sb + SM_W1HI +
                    (uint32_t)((nt2 * 16 + brow) * RS + kk * 16 + bcol) * 2;
                uint32_t bhi[4], blo[4];
                ldsm4(bhi, bAddr);
                ldsm4(blo, bAddr + WT);
                mma16816(c1[2 * nt2],     ahi, bhi[0], bhi[1]);
                mma16816(c1[2 * nt2],     ahi, blo[0], blo[1]);
                mma16816(c1[2 * nt2],     alo, bhi[0], bhi[1]);
                mma16816(c1[2 * nt2 + 1], ahi, bhi[2], bhi[3]);
                mma16816(c1[2 * nt2 + 1], ahi, blo[2], blo[3]);
                mma16816(c1[2 * nt2 + 1], alo, bhi[2], bhi[3]);
            }
        }

        // ---- hidden = relu(c1 + b1), re-fragmented in registers ----
        uint32_t hh[8][4], hl[8][4];
        #pragma unroll
        for (int j = 0; j < 8; j++) {
            float be0 = b1s[16 * j + m2],     be1 = b1s[16 * j + m2 + 1];
            float bo0 = b1s[16 * j + 8 + m2], bo1 = b1s[16 * j + 8 + m2 + 1];
            split2(fmaxf(c1[2 * j][0] + be0, 0.f),
                   fmaxf(c1[2 * j][1] + be1, 0.f), hh[j][0], hl[j][0]);
            split2(fmaxf(c1[2 * j][2] + be0, 0.f),
                   fmaxf(c1[2 * j][3] + be1, 0.f), hh[j][1], hl[j][1]);
            split2(fmaxf(c1[2 * j + 1][0] + bo0, 0.f),
                   fmaxf(c1[2 * j + 1][1] + bo1, 0.f), hh[j][2], hl[j][2]);
            split2(fmaxf(c1[2 * j + 1][2] + bo0, 0.f),
                   fmaxf(c1[2 * j + 1][3] + bo1, 0.f), hh[j][3], hl[j][3]);
        }

        // ---- layer 2 in two n-halves (c2 = 32 regs), W2 from smem ----
        #pragma unroll
        for (int h = 0; h < 2; h++) {
            float c2[8][4];
            #pragma unroll
            for (int i = 0; i < 8; i++)
                c2[i][0] = c2[i][1] = c2[i][2] = c2[i][3] = 0.f;

            #pragma unroll
            for (int kk = 0; kk < 8; kk++) {
                #pragma unroll
                for (int i = 0; i < 4; i++) {
                    int nt2 = h * 4 + i;
                    uint32_t bAddr = sb + SM_W2HI +
                        (uint32_t)((nt2 * 16 + brow) * RS + kk * 16 + bcol) * 2;
                    uint32_t bhi[4], blo[4];
                    ldsm4(bhi, bAddr);
                    ldsm4(blo, bAddr + WT);
                    mma16816(c2[2 * i],     hh[kk], bhi[0], bhi[1]);
                    mma16816(c2[2 * i],     hh[kk], blo[0], blo[1]);
                    mma16816(c2[2 * i],     hl[kk], bhi[0], bhi[1]);
                    mma16816(c2[2 * i + 1], hh[kk], bhi[2], bhi[3]);
                    mma16816(c2[2 * i + 1], hh[kk], blo[2], blo[3]);
                    mma16816(c2[2 * i + 1], hl[kk], bhi[2], bhi[3]);
                }
            }

            #pragma unroll
            for (int nt = 0; nt < 8; nt++) {
                int col = (h * 8 + nt) * 8 + m2;
                float bb0 = b2s[col], bb1 = b2s[col + 1];
                if (val0)
                    *reinterpret_cast<float2*>(out + (size_t)r0 * D + col) =
                        make_float2(c2[nt][0] + bb0, c2[nt][1] + bb1);
                if (val1)
                    *reinterpret_cast<float2*>(out + (size_t)r1 * D + col) =
                        make_float2(c2[nt][2] + bb0, c2[nt][3] + bb1);
            }
        }
    }
}

// ---------------------------------------------------------------------------
// launch: setup (prep + eps-scaled init) -> scatter -> persistent HMMA MLP
// ---------------------------------------------------------------------------
extern "C" void kernel_launch(void* const* d_in, const int* in_sizes, int n_in,
                              void* d_out, int out_size) {
    const float* x   = (const float*)d_in[0];
    const float* ea  = (const float*)d_in[1];
    const float* W1  = (const float*)d_in[2];
    const float* b1  = (const float*)d_in[3];
    const float* W2  = (const float*)d_in[4];
    const float* b2  = (const float*)d_in[5];
    const float* eps = (const float*)d_in[6];
    const int*   ei  = (const int*)d_in[7];

    int N = in_sizes[0] / D;
    int E = in_sizes[1] / D;

    int ninit4 = N * D / 4;
    int setup_blocks = 128 + (ninit4 + 255) / 256;
    setup_kernel<<<setup_blocks, 256>>>(W1, W2, x, eps, ninit4);

    long long scatter_threads = (long long)E * 32;
    scatter_kernel<<<(int)((scatter_threads + 255) / 256), 256>>>(x, ea, ei, E);

    cudaFuncSetAttribute(mlp_kernel,
                         cudaFuncAttributeMaxDynamicSharedMemorySize, SM_TOTAL);
    int ntiles = (N + 255) / 256;
    int grid = ntiles < 152 ? ntiles : 152;
    mlp_kernel<<<grid, 512, SM_TOTAL>>>(b1, b2, (float*)d_out, N, ntiles);
}

// round 14
// speedup vs baseline: 1.0842x; 1.0664x over previous
#include <cuda_runtime.h>
#include <cuda_fp16.h>
#include <cstdint>

static constexpr int D = 128;       // feature dim == hidden dim
static constexpr int MAXN = 100000;

// accumulator: initialized to (1+eps)*x by setup, then scatter adds messages
__device__ __align__(128) float g_acc[(size_t)MAXN * D];
// fp16 weights, transposed to [n][k] row-major, 128x128 each (no lo needed:
// A is fp16-split 2-term => only dropped term is Ah*Blo ~ 2^-12.8)
__device__ __align__(16) __half g_w1h[16384];
__device__ __align__(16) __half g_w2h[16384];

// ---------------------------------------------------------------------------
// helpers
// ---------------------------------------------------------------------------
__device__ __forceinline__ uint32_t smem_to_u32(const void* p) {
    uint32_t a;
    asm("{ .reg .u64 t; cvta.to.shared.u64 t, %1; cvt.u32.u64 %0, t; }"
        : "=r"(a) : "l"(p));
    return a;
}
__device__ __forceinline__ void ldsm4(uint32_t r[4], uint32_t addr) {
    asm volatile("ldmatrix.sync.aligned.m8n8.x4.shared.b16 {%0,%1,%2,%3}, [%4];"
                 : "=r"(r[0]), "=r"(r[1]), "=r"(r[2]), "=r"(r[3]) : "r"(addr));
}
__device__ __forceinline__ void mma16816h(float c[4], const uint32_t a[4],
                                          uint32_t b0, uint32_t b1) {
    asm volatile("mma.sync.aligned.m16n8k16.row.col.f32.f16.f16.f32 "
                 "{%0,%1,%2,%3}, {%4,%5,%6,%7}, {%8,%9}, {%0,%1,%2,%3};"
                 : "+f"(c[0]), "+f"(c[1]), "+f"(c[2]), "+f"(c[3])
                 : "r"(a[0]), "r"(a[1]), "r"(a[2]), "r"(a[3]),
                   "r"(b0), "r"(b1));
}
// split two floats into packed fp16x2 hi + lo words (A exact to 2^-22)
__device__ __forceinline__ void split2h(float v0, float v1,
                                        uint32_t& hp, uint32_t& lp) {
    __half h0 = __float2half_rn(v0);
    __half h1 = __float2half_rn(v1);
    __half l0 = __float2half_rn(v0 - __half2float(h0));
    __half l1 = __float2half_rn(v1 - __half2float(h1));
    hp = (uint32_t)__half_as_ushort(h0) |
         ((uint32_t)__half_as_ushort(h1) << 16);
    lp = (uint32_t)__half_as_ushort(l0) |
         ((uint32_t)__half_as_ushort(l1) << 16);
}
// x row load pinned in L2 via cache-hint policy (evict_last) — R8-proven
__device__ __forceinline__ float4 ldg_keep(const float4* p, uint64_t pol) {
    float4 v;
    asm volatile("ld.global.nc.L2::cache_hint.v4.f32 {%0,%1,%2,%3}, [%4], %5;"
                 : "=f"(v.x), "=f"(v.y), "=f"(v.z), "=f"(v.w)
                 : "l"(p), "l"(pol));
    return v;
}

// ---------------------------------------------------------------------------
// setup: blocks [0,64) convert weights to fp16 [n][k]; rest: acc = (1+eps)*x
// ---------------------------------------------------------------------------
__global__ void setup_kernel(const float* __restrict__ W1,
                             const float* __restrict__ W2,
                             const float* __restrict__ x,
                             const float* __restrict__ eps, int ninit4) {
    int b = blockIdx.x, t = threadIdx.x;
    if (b < 128) {
        int idx = b * 256 + t;           // 0..32767
        int m = idx >> 14;
        int r = idx & 16383;
        int k = r >> 7, n = r & 127;
        float w = (m ? W2 : W1)[k * 128 + n];
        __half h = __float2half_rn(w);
        int e = n * 128 + k;
        if (m) g_w2h[e] = h;
        else   g_w1h[e] = h;
    } else {
        int i = (b - 128) * 256 + t;
        if (i < ninit4) {
            float s = 1.0f + *eps;
            float4 v = reinterpret_cast<const float4*>(x)[i];
            v.x *= s; v.y *= s; v.z *= s; v.w *= s;
            reinterpret_cast<float4*>(g_acc)[i] = v;
        }
    }
}

// ---------------------------------------------------------------------------
// scatter: EXACT R8/R11 form (204.9 us proven): one warp per edge, red.v4
// into g_acc; x pinned evict_last, ea streamed evict-first
// ---------------------------------------------------------------------------
__global__ void scatter_kernel(const float* __restrict__ x,
                               const float* __restrict__ ea,
                               const int* __restrict__ ei, int E) {
    int gtid = blockIdx.x * blockDim.x + threadIdx.x;
    int e = gtid >> 5;
    int lane = gtid & 31;
    if (e >= E) return;

    uint64_t pol;
    asm volatile("createpolicy.fractional.L2::evict_last.b64 %0, 1.0;"
                 : "=l"(pol));

    int u = ei[e];
    int v = ei[E + e];

    float4 a  = __ldcs(reinterpret_cast<const float4*>(ea + (size_t)e * D) + lane);
    float4 xu = ldg_keep(reinterpret_cast<const float4*>(x + (size_t)u * D) + lane, pol);
    float4 xv = ldg_keep(reinterpret_cast<const float4*>(x + (size_t)v * D) + lane, pol);

    float4 mu, mv;
    mu.x = fmaxf(xv.x + a.x, 0.0f); mu.y = fmaxf(xv.y + a.y, 0.0f);
    mu.z = fmaxf(xv.z + a.z, 0.0f); mu.w = fmaxf(xv.w + a.w, 0.0f);
    mv.x = fmaxf(xu.x + a.x, 0.0f); mv.y = fmaxf(xu.y + a.y, 0.0f);
    mv.z = fmaxf(xu.z + a.z, 0.0f); mv.w = fmaxf(xu.w + a.w, 0.0f);

    float* pu = g_acc + (size_t)u * D + lane * 4;
    float* pv = g_acc + (size_t)v * D + lane * 4;
    asm volatile("red.global.add.v4.f32 [%0], {%1,%2,%3,%4};"
                 :: "l"(pu), "f"(mu.x), "f"(mu.y), "f"(mu.z), "f"(mu.w) : "memory");
    asm volatile("red.global.add.v4.f32 [%0], {%1,%2,%3,%4};"
                 :: "l"(pv), "f"(mv.x), "f"(mv.y), "f"(mv.z), "f"(mv.w) : "memory");
}

// ---------------------------------------------------------------------------
// PERSISTENT fused MLP on HMMA fp16 (2-pass split: AhBh + AlBh; B single fp16)
// 256 threads / 8 warps per CTA, 2 CTAs/SM; W1h+W2h staged in smem ONCE;
// grid-stride over 128-row tiles. MMA count -33%, B ldsm -50% vs bf16 3-pass.
// ---------------------------------------------------------------------------
static constexpr int RS = 136;                        // row stride (fp16)
static constexpr int WT = 128 * RS * 2;               // 34816 B per tile
static constexpr int SM_W1H = 0;
static constexpr int SM_W2H = SM_W1H + WT;
static constexpr int SM_B1  = SM_W2H + WT;            // 69632
static constexpr int SM_B2  = SM_B1 + 512;
static constexpr int SM_TOTAL = SM_B2 + 512;          // 70656 B

__device__ __forceinline__ void copy_w256(char* smem, int dst,
                                          const __half* src, int tid) {
    const uint4* s = reinterpret_cast<const uint4*>(src);
    #pragma unroll
    for (int i = tid; i < 2048; i += 256) {
        int r = i >> 4, c8 = i & 15;
        *reinterpret_cast<uint4*>(smem + dst + (r * RS + c8 * 8) * 2) = s[i];
    }
}

__device__ __forceinline__ void load_splith(const float* ap, bool valid, int k,
                                            uint32_t& hp, uint32_t& lp) {
    float v0 = 0.f, v1 = 0.f;
    if (valid) {
        float2 p = *reinterpret_cast<const float2*>(ap + k);
        v0 = p.x; v1 = p.y;
    }
    split2h(v0, v1, hp, lp);
}

__global__ void __launch_bounds__(256, 2)
mlp_kernel(const float* __restrict__ b1, const float* __restrict__ b2,
           float* __restrict__ out, int N, int ntiles) {
    extern __shared__ char smem[];
    uint32_t sb = smem_to_u32(smem);
    int tid = threadIdx.x;
    int wid = tid >> 5;
    int lane = tid & 31;

    copy_w256(smem, SM_W1H, g_w1h, tid);
    copy_w256(smem, SM_W2H, g_w2h, tid);
    if (tid < 128) {
        reinterpret_cast<float*>(smem + SM_B1)[tid] = b1[tid];
        reinterpret_cast<float*>(smem + SM_B2)[tid] = b2[tid];
    }
    __syncthreads();     // only barrier in the kernel

    int m2 = (lane & 3) * 2;
    int g  = lane >> 2;
    int brow = (lane & 7) + ((lane & 16) ? 8 : 0);
    int bcol = (lane & 8) ? 8 : 0;
    const float* b1s = reinterpret_cast<const float*>(smem + SM_B1);
    const float* b2s = reinterpret_cast<const float*>(smem + SM_B2);

    for (int tile = blockIdx.x; tile < ntiles; tile += gridDim.x) {
        int row0 = tile * 128;
        int r0 = row0 + wid * 16 + g;
        int r1 = r0 + 8;
        bool val0 = r0 < N, val1 = r1 < N;
        const float* a0p = g_acc + (size_t)r0 * D;
        const float* a1p = g_acc + (size_t)r1 * D;

        float c1[16][4];
        #pragma unroll
        for (int i = 0; i < 16; i++)
            c1[i][0] = c1[i][1] = c1[i][2] = c1[i][3] = 0.f;

        // ---- layer 1: A (fp16 hi+lo) from gmem, W1h from smem ----
        #pragma unroll 2
        for (int kk = 0; kk < 8; kk++) {
            int k0 = kk * 16 + m2;
            uint32_t ahi[4], alo[4];
            load_splith(a0p, val0, k0,     ahi[0], alo[0]);
            load_splith(a1p, val1, k0,     ahi[1], alo[1]);
            load_splith(a0p, val0, k0 + 8, ahi[2], alo[2]);
            load_splith(a1p, val1, k0 + 8, ahi[3], alo[3]);
            #pragma unroll
            for (int nt2 = 0; nt2 < 8; nt2++) {
                uint32_t bAddr = sb + SM_W1H +
                    (uint32_t)((nt2 * 16 + brow) * RS + kk * 16 + bcol) * 2;
                uint32_t bh[4];
                ldsm4(bh, bAddr);
                mma16816h(c1[2 * nt2],     ahi, bh[0], bh[1]);
                mma16816h(c1[2 * nt2],     alo, bh[0], bh[1]);
                mma16816h(c1[2 * nt2 + 1], ahi, bh[2], bh[3]);
                mma16816h(c1[2 * nt2 + 1], alo, bh[2], bh[3]);
            }
        }

        // ---- hidden = relu(c1 + b1), re-fragmented (fp16 hi+lo) ----
        uint32_t hh[8][4], hl[8][4];
        #pragma unroll
        for (int j = 0; j < 8; j++) {
            float be0 = b1s[16 * j + m2],     be1 = b1s[16 * j + m2 + 1];
            float bo0 = b1s[16 * j + 8 + m2], bo1 = b1s[16 * j + 8 + m2 + 1];
            split2h(fmaxf(c1[2 * j][0] + be0, 0.f),
                    fmaxf(c1[2 * j][1] + be1, 0.f), hh[j][0], hl[j][0]);
            split2h(fmaxf(c1[2 * j][2] + be0, 0.f),
                    fmaxf(c1[2 * j][3] + be1, 0.f), hh[j][1], hl[j][1]);
            split2h(fmaxf(c1[2 * j + 1][0] + bo0, 0.f),
                    fmaxf(c1[2 * j + 1][1] + bo1, 0.f), hh[j][2], hl[j][2]);
            split2h(fmaxf(c1[2 * j + 1][2] + bo0, 0.f),
                    fmaxf(c1[2 * j + 1][3] + bo1, 0.f), hh[j][3], hl[j][3]);
        }

        // ---- layer 2 in two n-halves (c2 = 32 regs), W2h from smem ----
        #pragma unroll
        for (int h = 0; h < 2; h++) {
            float c2[8][4];
            #pragma unroll
            for (int i = 0; i < 8; i++)
                c2[i][0] = c2[i][1] = c2[i][2] = c2[i][3] = 0.f;

            #pragma unroll
            for (int kk = 0; kk < 8; kk++) {
                #pragma unroll
                for (int i = 0; i < 4; i++) {
                    int nt2 = h * 4 + i;
                    uint32_t bAddr = sb + SM_W2H +
                        (uint32_t)((nt2 * 16 + brow) * RS + kk * 16 + bcol) * 2;
                    uint32_t bh[4];
                    ldsm4(bh, bAddr);
                    mma16816h(c2[2 * i],     hh[kk], bh[0], bh[1]);
                    mma16816h(c2[2 * i],     hl[kk], bh[0], bh[1]);
                    mma16816h(c2[2 * i + 1], hh[kk], bh[2], bh[3]);
                    mma16816h(c2[2 * i + 1], hl[kk], bh[2], bh[3]);
                }
            }

            #pragma unroll
            for (int nt = 0; nt < 8; nt++) {
                int col = (h * 8 + nt) * 8 + m2;
                float bb0 = b2s[col], bb1 = b2s[col + 1];
                if (val0)
                    *reinterpret_cast<float2*>(out + (size_t)r0 * D + col) =
                        make_float2(c2[nt][0] + bb0, c2[nt][1] + bb1);
                if (val1)
                    *reinterpret_cast<float2*>(out + (size_t)r1 * D + col) =
                        make_float2(c2[nt][2] + bb0, c2[nt][3] + bb1);
            }
        }
    }
}

// ---------------------------------------------------------------------------
// launch: setup (prep + eps-scaled init) -> scatter -> persistent fp16 MLP
// ---------------------------------------------------------------------------
extern "C" void kernel_launch(void* const* d_in, const int* in_sizes, int n_in,
                              void* d_out, int out_size) {
    const float* x   = (const float*)d_in[0];
    const float* ea  = (const float*)d_in[1];
    const float* W1  = (const float*)d_in[2];
    const float* b1  = (const float*)d_in[3];
    const float* W2  = (const float*)d_in[4];
    const float* b2  = (const float*)d_in[5];
    const float* eps = (const float*)d_in[6];
    const int*   ei  = (const int*)d_in[7];

    int N = in_sizes[0] / D;
    int E = in_sizes[1] / D;

    int ninit4 = N * D / 4;
    int setup_blocks = 128 + (ninit4 + 255) / 256;
    setup_kernel<<<setup_blocks, 256>>>(W1, W2, x, eps, ninit4);

    long long scatter_threads = (long long)E * 32;
    scatter_kernel<<<(int)((scatter_threads + 255) / 256), 256>>>(x, ea, ei, E);

    cudaFuncSetAttribute(mlp_kernel,
                         cudaFuncAttributeMaxDynamicSharedMemorySize, SM_TOTAL);
    int ntiles = (N + 127) / 128;
    int grid = ntiles < 304 ? ntiles : 304;
    mlp_kernel<<<grid, 256, SM_TOTAL>>>(b1, b2, (float*)d_out, N, ntiles);
}

// round 15
// speedup vs baseline: 1.0942x; 1.0092x over previous
#include <cuda_runtime.h>
#include <cuda_fp16.h>
#include <cstdint>

static constexpr int D = 128;       // feature dim == hidden dim
static constexpr int MAXN = 100000;

// accumulator: initialized to (1+eps)*x by setup, then scatter adds messages
__device__ __align__(128) float g_acc[(size_t)MAXN * D];
// fp16 weights, transposed to [n][k] row-major, 128x128 each
__device__ __align__(16) __half g_w1h[16384];
__device__ __align__(16) __half g_w2h[16384];

// ---------------------------------------------------------------------------
// helpers
// ---------------------------------------------------------------------------
__device__ __forceinline__ uint32_t smem_to_u32(const void* p) {
    uint32_t a;
    asm("{ .reg .u64 t; cvta.to.shared.u64 t, %1; cvt.u32.u64 %0, t; }"
        : "=r"(a) : "l"(p));
    return a;
}
__device__ __forceinline__ void ldsm4(uint32_t r[4], uint32_t addr) {
    asm volatile("ldmatrix.sync.aligned.m8n8.x4.shared.b16 {%0,%1,%2,%3}, [%4];"
                 : "=r"(r[0]), "=r"(r[1]), "=r"(r[2]), "=r"(r[3]) : "r"(addr));
}
__device__ __forceinline__ void mma16816h(float c[4], const uint32_t a[4],
                                          uint32_t b0, uint32_t b1) {
    asm volatile("mma.sync.aligned.m16n8k16.row.col.f32.f16.f16.f32 "
                 "{%0,%1,%2,%3}, {%4,%5,%6,%7}, {%8,%9}, {%0,%1,%2,%3};"
                 : "+f"(c[0]), "+f"(c[1]), "+f"(c[2]), "+f"(c[3])
                 : "r"(a[0]), "r"(a[1]), "r"(a[2]), "r"(a[3]),
                   "r"(b0), "r"(b1));
}
// split two floats into packed fp16x2 hi + lo words — packed-cvt fast path
__device__ __forceinline__ void split2h(float v0, float v1,
                                        uint32_t& hp, uint32_t& lp) {
    asm("cvt.rn.f16x2.f32 %0, %1, %2;" : "=r"(hp) : "f"(v1), "f"(v0));
    __half2 h2 = *reinterpret_cast<__half2*>(&hp);
    float2 hf = __half22float2(h2);          // hf.x = h0, hf.y = h1
    float l0 = v0 - hf.x;
    float l1 = v1 - hf.y;
    asm("cvt.rn.f16x2.f32 %0, %1, %2;" : "=r"(lp) : "f"(l1), "f"(l0));
}
// x row load pinned in L2 via cache-hint policy (evict_last) — R8-proven
__device__ __forceinline__ float4 ldg_keep(const float4* p, uint64_t pol) {
    float4 v;
    asm volatile("ld.global.nc.L2::cache_hint.v4.f32 {%0,%1,%2,%3}, [%4], %5;"
                 : "=f"(v.x), "=f"(v.y), "=f"(v.z), "=f"(v.w)
                 : "l"(p), "l"(pol));
    return v;
}

// ---------------------------------------------------------------------------
// setup: blocks [0,128) convert weights to fp16 [n][k]; rest: acc = (1+eps)*x
// ---------------------------------------------------------------------------
__global__ void setup_kernel(const float* __restrict__ W1,
                             const float* __restrict__ W2,
                             const float* __restrict__ x,
                             const float* __restrict__ eps, int ninit4) {
    int b = blockIdx.x, t = threadIdx.x;
    if (b < 128) {
        int idx = b * 256 + t;           // 0..32767
        int m = idx >> 14;
        int r = idx & 16383;
        int k = r >> 7, n = r & 127;
        float w = (m ? W2 : W1)[k * 128 + n];
        __half h = __float2half_rn(w);
        int e = n * 128 + k;
        if (m) g_w2h[e] = h;
        else   g_w1h[e] = h;
    } else {
        int i = (b - 128) * 256 + t;
        if (i < ninit4) {
            float s = 1.0f + *eps;
            float4 v = reinterpret_cast<const float4*>(x)[i];
            v.x *= s; v.y *= s; v.z *= s; v.w *= s;
            reinterpret_cast<float4*>(g_acc)[i] = v;
        }
    }
}

// ---------------------------------------------------------------------------
// scatter: EXACT R8/R14 form (proven): one warp per edge, red.v4 into g_acc;
// x pinned evict_last, ea streamed evict-first
// ---------------------------------------------------------------------------
__global__ void scatter_kernel(const float* __restrict__ x,
                               const float* __restrict__ ea,
                               const int* __restrict__ ei, int E) {
    int gtid = blockIdx.x * blockDim.x + threadIdx.x;
    int e = gtid >> 5;
    int lane = gtid & 31;
    if (e >= E) return;

    uint64_t pol;
    asm volatile("createpolicy.fractional.L2::evict_last.b64 %0, 1.0;"
                 : "=l"(pol));

    int u = ei[e];
    int v = ei[E + e];

    float4 a  = __ldcs(reinterpret_cast<const float4*>(ea + (size_t)e * D) + lane);
    float4 xu = ldg_keep(reinterpret_cast<const float4*>(x + (size_t)u * D) + lane, pol);
    float4 xv = ldg_keep(reinterpret_cast<const float4*>(x + (size_t)v * D) + lane, pol);

    float4 mu, mv;
    mu.x = fmaxf(xv.x + a.x, 0.0f); mu.y = fmaxf(xv.y + a.y, 0.0f);
    mu.z = fmaxf(xv.z + a.z, 0.0f); mu.w = fmaxf(xv.w + a.w, 0.0f);
    mv.x = fmaxf(xu.x + a.x, 0.0f); mv.y = fmaxf(xu.y + a.y, 0.0f);
    mv.z = fmaxf(xu.z + a.z, 0.0f); mv.w = fmaxf(xu.w + a.w, 0.0f);

    float* pu = g_acc + (size_t)u * D + lane * 4;
    float* pv = g_acc + (size_t)v * D + lane * 4;
    asm volatile("red.global.add.v4.f32 [%0], {%1,%2,%3,%4};"
                 :: "l"(pu), "f"(mu.x), "f"(mu.y), "f"(mu.z), "f"(mu.w) : "memory");
    asm volatile("red.global.add.v4.f32 [%0], {%1,%2,%3,%4};"
                 :: "l"(pv), "f"(mv.x), "f"(mv.y), "f"(mv.z), "f"(mv.w) : "memory");
}

// ---------------------------------------------------------------------------
// PERSISTENT fused MLP on HMMA fp16 (2-pass split: AhBh + AlBh)
// 256 threads / 8 warps per CTA, 2 CTAs/SM; W1h+W2h staged in smem ONCE;
// grid-stride over 128-row tiles. Layer-1 software-pipelined: next-kk A
// loads issued one full MMA block ahead.
// ---------------------------------------------------------------------------
static constexpr int RS = 136;                        // row stride (fp16)
static constexpr int WT = 128 * RS * 2;               // 34816 B per tile
static constexpr int SM_W1H = 0;
static constexpr int SM_W2H = SM_W1H + WT;
static constexpr int SM_B1  = SM_W2H + WT;            // 69632
static constexpr int SM_B2  = SM_B1 + 512;
static constexpr int SM_TOTAL = SM_B2 + 512;          // 70656 B

__device__ __forceinline__ void copy_w256(char* smem, int dst,
                                          const __half* src, int tid) {
    const uint4* s = reinterpret_cast<const uint4*>(src);
    #pragma unroll
    for (int i = tid; i < 2048; i += 256) {
        int r = i >> 4, c8 = i & 15;
        *reinterpret_cast<uint4*>(smem + dst + (r * RS + c8 * 8) * 2) = s[i];
    }
}

__device__ __forceinline__ float2 ld2(const float* ap, bool valid, int k) {
    return valid ? *reinterpret_cast<const float2*>(ap + k)
                 : make_float2(0.f, 0.f);
}

__global__ void __launch_bounds__(256, 2)
mlp_kernel(const float* __restrict__ b1, const float* __restrict__ b2,
           float* __restrict__ out, int N, int ntiles) {
    extern __shared__ char smem[];
    uint32_t sb = smem_to_u32(smem);
    int tid = threadIdx.x;
    int wid = tid >> 5;
    int lane = tid & 31;

    copy_w256(smem, SM_W1H, g_w1h, tid);
    copy_w256(smem, SM_W2H, g_w2h, tid);
    if (tid < 128) {
        reinterpret_cast<float*>(smem + SM_B1)[tid] = b1[tid];
        reinterpret_cast<float*>(smem + SM_B2)[tid] = b2[tid];
    }
    __syncthreads();     // only barrier in the kernel

    int m2 = (lane & 3) * 2;
    int g  = lane >> 2;
    int brow = (lane & 7) + ((lane & 16) ? 8 : 0);
    int bcol = (lane & 8) ? 8 : 0;
    const float* b1s = reinterpret_cast<const float*>(smem + SM_B1);
    const float* b2s = reinterpret_cast<const float*>(smem + SM_B2);

    for (int tile = blockIdx.x; tile < ntiles; tile += gridDim.x) {
        int row0 = tile * 128;
        int r0 = row0 + wid * 16 + g;
        int r1 = r0 + 8;
        bool val0 = r0 < N, val1 = r1 < N;
        const float* a0p = g_acc + (size_t)r0 * D;
        const float* a1p = g_acc + (size_t)r1 * D;

        float c1[16][4];
        #pragma unroll
        for (int i = 0; i < 16; i++)
            c1[i][0] = c1[i][1] = c1[i][2] = c1[i][3] = 0.f;

        // ---- layer 1: software-pipelined A loads + HMMA ----
        float2 raw0 = ld2(a0p, val0, m2);
        float2 raw1 = ld2(a1p, val1, m2);
        float2 raw2 = ld2(a0p, val0, m2 + 8);
        float2 raw3 = ld2(a1p, val1, m2 + 8);
        #pragma unroll
        for (int kk = 0; kk < 8; kk++) {
            uint32_t ahi[4], alo[4];
            split2h(raw0.x, raw0.y, ahi[0], alo[0]);
            split2h(raw1.x, raw1.y, ahi[1], alo[1]);
            split2h(raw2.x, raw2.y, ahi[2], alo[2]);
            split2h(raw3.x, raw3.y, ahi[3], alo[3]);
            if (kk < 7) {
                int kn = (kk + 1) * 16 + m2;
                raw0 = ld2(a0p, val0, kn);
                raw1 = ld2(a1p, val1, kn);
                raw2 = ld2(a0p, val0, kn + 8);
                raw3 = ld2(a1p, val1, kn + 8);
            }
            #pragma unroll
            for (int nt2 = 0; nt2 < 8; nt2++) {
                uint32_t bAddr = sb + SM_W1H +
                    (uint32_t)((nt2 * 16 + brow) * RS + kk * 16 + bcol) * 2;
                uint32_t bh[4];
                ldsm4(bh, bAddr);
                mma16816h(c1[2 * nt2],     ahi, bh[0], bh[1]);
                mma16816h(c1[2 * nt2],     alo, bh[0], bh[1]);
                mma16816h(c1[2 * nt2 + 1], ahi, bh[2], bh[3]);
                mma16816h(c1[2 * nt2 + 1], alo, bh[2], bh[3]);
            }
        }

        // ---- hidden = relu(c1 + b1), re-fragmented (fp16 hi+lo) ----
        uint32_t hh[8][4], hl[8][4];
        #pragma unroll
        for (int j = 0; j < 8; j++) {
            float be0 = b1s[16 * j + m2],     be1 = b1s[16 * j + m2 + 1];
            float bo0 = b1s[16 * j + 8 + m2], bo1 = b1s[16 * j + 8 + m2 + 1];
            split2h(fmaxf(c1[2 * j][0] + be0, 0.f),
                    fmaxf(c1[2 * j][1] + be1, 0.f), hh[j][0], hl[j][0]);
            split2h(fmaxf(c1[2 * j][2] + be0, 0.f),
                    fmaxf(c1[2 * j][3] + be1, 0.f), hh[j][1], hl[j][1]);
            split2h(fmaxf(c1[2 * j + 1][0] + bo0, 0.f),
                    fmaxf(c1[2 * j + 1][1] + bo1, 0.f), hh[j][2], hl[j][2]);
            split2h(fmaxf(c1[2 * j + 1][2] + bo0, 0.f),
                    fmaxf(c1[2 * j + 1][3] + bo1, 0.f), hh[j][3], hl[j][3]);
        }

        // ---- layer 2 in two n-halves (c2 = 32 regs), W2h from smem ----
        #pragma unroll
        for (int h = 0; h < 2; h++) {
            float c2[8][4];
            #pragma unroll
            for (int i = 0; i < 8; i++)
                c2[i][0] = c2[i][1] = c2[i][2] = c2[i][3] = 0.f;

            #pragma unroll
            for (int kk = 0; kk < 8; kk++) {
                #pragma unroll
                for (int i = 0; i < 4; i++) {
                    int nt2 = h * 4 + i;
                    uint32_t bAddr = sb + SM_W2H +
                        (uint32_t)((nt2 * 16 + brow) * RS + kk * 16 + bcol) * 2;
                    uint32_t bh[4];
                    ldsm4(bh, bAddr);
                    mma16816h(c2[2 * i],     hh[kk], bh[0], bh[1]);
                    mma16816h(c2[2 * i],     hl[kk], bh[0], bh[1]);
                    mma16816h(c2[2 * i + 1], hh[kk], bh[2], bh[3]);
                    mma16816h(c2[2 * i + 1], hl[kk], bh[2], bh[3]);
                }
            }

            #pragma unroll
            for (int nt = 0; nt < 8; nt++) {
                int col = (h * 8 + nt) * 8 + m2;
                float bb0 = b2s[col], bb1 = b2s[col + 1];
                if (val0)
                    *reinterpret_cast<float2*>(out + (size_t)r0 * D + col) =
                        make_float2(c2[nt][0] + bb0, c2[nt][1] + bb1);
                if (val1)
                    *reinterpret_cast<float2*>(out + (size_t)r1 * D + col) =
                        make_float2(c2[nt][2] + bb0, c2[nt][3] + bb1);
            }
        }
    }
}

// ---------------------------------------------------------------------------
// launch: setup (prep + eps-scaled init) -> scatter -> persistent fp16 MLP
// ---------------------------------------------------------------------------
extern "C" void kernel_launch(void* const* d_in, const int* in_sizes, int n_in,
                              void* d_out, int out_size) {
    const float* x   = (const float*)d_in[0];
    const float* ea  = (const float*)d_in[1];
    const float* W1  = (const float*)d_in[2];
    const float* b1  = (const float*)d_in[3];
    const float* W2  = (const float*)d_in[4];
    const float* b2  = (const float*)d_in[5];
    const float* eps = (const float*)d_in[6];
    const int*   ei  = (const int*)d_in[7];

    int N = in_sizes[0] / D;
    int E = in_sizes[1] / D;

    int ninit4 = N * D / 4;
    int setup_blocks = 128 + (ninit4 + 255) / 256;
    setup_kernel<<<setup_blocks, 256>>>(W1, W2, x, eps, ninit4);

    long long scatter_threads = (long long)E * 32;
    scatter_kernel<<<(int)((scatter_threads + 255) / 256), 256>>>(x, ea, ei, E);

    cudaFuncSetAttribute(mlp_kernel,
                         cudaFuncAttributeMaxDynamicSharedMemorySize, SM_TOTAL);
    int ntiles = (N + 127) / 128;
    int grid = ntiles < 304 ? ntiles : 304;
    mlp_kernel<<<grid, 256, SM_TOTAL>>>(b1, b2, (float*)d_out, N, ntiles);
}

// round 16
// speedup vs baseline: 1.1220x; 1.0254x over previous
#include <cuda_runtime.h>
#include <cuda_fp16.h>
#include <cstdint>

static constexpr int D = 128;       // feature dim == hidden dim
static constexpr int MAXN = 100000;

// accumulator: initialized to (1+eps)*x by setup, then scatter adds messages
__device__ __align__(128) float g_acc[(size_t)MAXN * D];
// fp16 weights, transposed to [n][k] row-major, 128x128 each
__device__ __align__(16) __half g_w1h[16384];
__device__ __align__(16) __half g_w2h[16384];

// ---------------------------------------------------------------------------
// helpers
// ---------------------------------------------------------------------------
__device__ __forceinline__ uint32_t smem_to_u32(const void* p) {
    uint32_t a;
    asm("{ .reg .u64 t; cvta.to.shared.u64 t, %1; cvt.u32.u64 %0, t; }"
        : "=r"(a) : "l"(p));
    return a;
}
__device__ __forceinline__ void ldsm4(uint32_t r[4], uint32_t addr) {
    asm volatile("ldmatrix.sync.aligned.m8n8.x4.shared.b16 {%0,%1,%2,%3}, [%4];"
                 : "=r"(r[0]), "=r"(r[1]), "=r"(r[2]), "=r"(r[3]) : "r"(addr));
}
__device__ __forceinline__ void mma16816h(float c[4], const uint32_t a[4],
                                          uint32_t b0, uint32_t b1) {
    asm volatile("mma.sync.aligned.m16n8k16.row.col.f32.f16.f16.f32 "
                 "{%0,%1,%2,%3}, {%4,%5,%6,%7}, {%8,%9}, {%0,%1,%2,%3};"
                 : "+f"(c[0]), "+f"(c[1]), "+f"(c[2]), "+f"(c[3])
                 : "r"(a[0]), "r"(a[1]), "r"(a[2]), "r"(a[3]),
                   "r"(b0), "r"(b1));
}
// split two floats into packed fp16x2 hi + lo words — packed-cvt fast path
__device__ __forceinline__ void split2h(float v0, float v1,
                                        uint32_t& hp, uint32_t& lp) {
    asm("cvt.rn.f16x2.f32 %0, %1, %2;" : "=r"(hp) : "f"(v1), "f"(v0));
    __half2 h2 = *reinterpret_cast<__half2*>(&hp);
    float2 hf = __half22float2(h2);
    float l0 = v0 - hf.x;
    float l1 = v1 - hf.y;
    asm("cvt.rn.f16x2.f32 %0, %1, %2;" : "=r"(lp) : "f"(l1), "f"(l0));
}
// single packed fp16x2 convert (no residual) — layer-2 hidden path
__device__ __forceinline__ uint32_t pack2h(float v0, float v1) {
    uint32_t hp;
    asm("cvt.rn.f16x2.f32 %0, %1, %2;" : "=r"(hp) : "f"(v1), "f"(v0));
    return hp;
}
// x row load pinned in L2 via cache-hint policy (evict_last)
__device__ __forceinline__ float4 ldg_keep(const float4* p, uint64_t pol) {
    float4 v;
    asm volatile("ld.global.nc.L2::cache_hint.v4.f32 {%0,%1,%2,%3}, [%4], %5;"
                 : "=f"(v.x), "=f"(v.y), "=f"(v.z), "=f"(v.w)
                 : "l"(p), "l"(pol));
    return v;
}

// ---------------------------------------------------------------------------
// setup: blocks [0,128) convert weights to fp16 [n][k]; rest: acc = (1+eps)*x
// x is read with evict_last => PRELOADS x into L2, pinned, for the scatter.
// ---------------------------------------------------------------------------
__global__ void setup_kernel(const float* __restrict__ W1,
                             const float* __restrict__ W2,
                             const float* __restrict__ x,
                             const float* __restrict__ eps, int ninit4) {
    int b = blockIdx.x, t = threadIdx.x;
    if (b < 128) {
        int idx = b * 256 + t;           // 0..32767
        int m = idx >> 14;
        int r = idx & 16383;
        int k = r >> 7, n = r & 127;
        float w = (m ? W2 : W1)[k * 128 + n];
        __half h = __float2half_rn(w);
        int e = n * 128 + k;
        if (m) g_w2h[e] = h;
        else   g_w1h[e] = h;
    } else {
        int i = (b - 128) * 256 + t;
        if (i < ninit4) {
            uint64_t pol;
            asm volatile("createpolicy.fractional.L2::evict_last.b64 %0, 1.0;"
                         : "=l"(pol));
            float s = 1.0f + *eps;
            float4 v = ldg_keep(reinterpret_cast<const float4*>(x) + i, pol);
            v.x *= s; v.y *= s; v.z *= s; v.w *= s;
            reinterpret_cast<float4*>(g_acc)[i] = v;
        }
    }
}

// ---------------------------------------------------------------------------
// scatter: EXACT R8/R14 form (proven): one warp per edge, red.v4 into g_acc;
// x pinned evict_last, ea streamed evict-first
// ---------------------------------------------------------------------------
__global__ void scatter_kernel(const float* __restrict__ x,
                               const float* __restrict__ ea,
                               const int* __restrict__ ei, int E) {
    int gtid = blockIdx.x * blockDim.x + threadIdx.x;
    int e = gtid >> 5;
    int lane = gtid & 31;
    if (e >= E) return;

    uint64_t pol;
    asm volatile("createpolicy.fractional.L2::evict_last.b64 %0, 1.0;"
                 : "=l"(pol));

    int u = ei[e];
    int v = ei[E + e];

    float4 a  = __ldcs(reinterpret_cast<const float4*>(ea + (size_t)e * D) + lane);
    float4 xu = ldg_keep(reinterpret_cast<const float4*>(x + (size_t)u * D) + lane, pol);
    float4 xv = ldg_keep(reinterpret_cast<const float4*>(x + (size_t)v * D) + lane, pol);

    float4 mu, mv;
    mu.x = fmaxf(xv.x + a.x, 0.0f); mu.y = fmaxf(xv.y + a.y, 0.0f);
    mu.z = fmaxf(xv.z + a.z, 0.0f); mu.w = fmaxf(xv.w + a.w, 0.0f);
    mv.x = fmaxf(xu.x + a.x, 0.0f); mv.y = fmaxf(xu.y + a.y, 0.0f);
    mv.z = fmaxf(xu.z + a.z, 0.0f); mv.w = fmaxf(xu.w + a.w, 0.0f);

    float* pu = g_acc + (size_t)u * D + lane * 4;
    float* pv = g_acc + (size_t)v * D + lane * 4;
    asm volatile("red.global.add.v4.f32 [%0], {%1,%2,%3,%4};"
                 :: "l"(pu), "f"(mu.x), "f"(mu.y), "f"(mu.z), "f"(mu.w) : "memory");
    asm volatile("red.global.add.v4.f32 [%0], {%1,%2,%3,%4};"
                 :: "l"(pv), "f"(mv.x), "f"(mv.y), "f"(mv.z), "f"(mv.w) : "memory");
}

// ---------------------------------------------------------------------------
// PERSISTENT fused MLP on HMMA fp16
// Layer 1: 2-pass A split (AhBh + AlBh) — acc needs the precision.
// Layer 2: single-pass (hidden as plain fp16) — dropped term ~2^-12.8.
// 256 threads / 8 warps per CTA, 2 CTAs/SM; W1h+W2h staged in smem ONCE;
// grid-stride over 128-row tiles; layer-1 A loads software-pipelined.
// ---------------------------------------------------------------------------
static constexpr int RS = 136;                        // row stride (fp16)
static constexpr int WT = 128 * RS * 2;               // 34816 B per tile
static constexpr int SM_W1H = 0;
static constexpr int SM_W2H = SM_W1H + WT;
static constexpr int SM_B1  = SM_W2H + WT;            // 69632
static constexpr int SM_B2  = SM_B1 + 512;
static constexpr int SM_TOTAL = SM_B2 + 512;          // 70656 B

__device__ __forceinline__ void copy_w256(char* smem, int dst,
                                          const __half* src, int tid) {
    const uint4* s = reinterpret_cast<const uint4*>(src);
    #pragma unroll
    for (int i = tid; i < 2048; i += 256) {
        int r = i >> 4, c8 = i & 15;
        *reinterpret_cast<uint4*>(smem + dst + (r * RS + c8 * 8) * 2) = s[i];
    }
}

__device__ __forceinline__ float2 ld2(const float* ap, bool valid, int k) {
    return valid ? *reinterpret_cast<const float2*>(ap + k)
                 : make_float2(0.f, 0.f);
}

__global__ void __launch_bounds__(256, 2)
mlp_kernel(const float* __restrict__ b1, const float* __restrict__ b2,
           float* __restrict__ out, int N, int ntiles) {
    extern __shared__ char smem[];
    uint32_t sb = smem_to_u32(smem);
    int tid = threadIdx.x;
    int wid = tid >> 5;
    int lane = tid & 31;

    copy_w256(smem, SM_W1H, g_w1h, tid);
    copy_w256(smem, SM_W2H, g_w2h, tid);
    if (tid < 128) {
        reinterpret_cast<float*>(smem + SM_B1)[tid] = b1[tid];
        reinterpret_cast<float*>(smem + SM_B2)[tid] = b2[tid];
    }
    __syncthreads();     // only barrier in the kernel

    int m2 = (lane & 3) * 2;
    int g  = lane >> 2;
    int brow = (lane & 7) + ((lane & 16) ? 8 : 0);
    int bcol = (lane & 8) ? 8 : 0;
    const float* b1s = reinterpret_cast<const float*>(smem + SM_B1);
    const float* b2s = reinterpret_cast<const float*>(smem + SM_B2);

    for (int tile = blockIdx.x; tile < ntiles; tile += gridDim.x) {
        int row0 = tile * 128;
        int r0 = row0 + wid * 16 + g;
        int r1 = r0 + 8;
        bool val0 = r0 < N, val1 = r1 < N;
        const float* a0p = g_acc + (size_t)r0 * D;
        const float* a1p = g_acc + (size_t)r1 * D;

        float c1[16][4];
        #pragma unroll
        for (int i = 0; i < 16; i++)
            c1[i][0] = c1[i][1] = c1[i][2] = c1[i][3] = 0.f;

        // ---- layer 1: software-pipelined A loads + HMMA (2-pass split) ----
        float2 raw0 = ld2(a0p, val0, m2);
        float2 raw1 = ld2(a1p, val1, m2);
        float2 raw2 = ld2(a0p, val0, m2 + 8);
        float2 raw3 = ld2(a1p, val1, m2 + 8);
        #pragma unroll
        for (int kk = 0; kk < 8; kk++) {
            uint32_t ahi[4], alo[4];
            split2h(raw0.x, raw0.y, ahi[0], alo[0]);
            split2h(raw1.x, raw1.y, ahi[1], alo[1]);
            split2h(raw2.x, raw2.y, ahi[2], alo[2]);
            split2h(raw3.x, raw3.y, ahi[3], alo[3]);
            if (kk < 7) {
                int kn = (kk + 1) * 16 + m2;
                raw0 = ld2(a0p, val0, kn);
                raw1 = ld2(a1p, val1, kn);
                raw2 = ld2(a0p, val0, kn + 8);
                raw3 = ld2(a1p, val1, kn + 8);
            }
            #pragma unroll
            for (int nt2 = 0; nt2 < 8; nt2++) {
                uint32_t bAddr = sb + SM_W1H +
                    (uint32_t)((nt2 * 16 + brow) * RS + kk * 16 + bcol) * 2;
                uint32_t bh[4];
                ldsm4(bh, bAddr);
                mma16816h(c1[2 * nt2],     ahi, bh[0], bh[1]);
                mma16816h(c1[2 * nt2],     alo, bh[0], bh[1]);
                mma16816h(c1[2 * nt2 + 1], ahi, bh[2], bh[3]);
                mma16816h(c1[2 * nt2 + 1], alo, bh[2], bh[3]);
            }
        }

        // ---- hidden = relu(c1 + b1), single fp16 fragment ----
        uint32_t hh[8][4];
        #pragma unroll
        for (int j = 0; j < 8; j++) {
            float be0 = b1s[16 * j + m2],     be1 = b1s[16 * j + m2 + 1];
            float bo0 = b1s[16 * j + 8 + m2], bo1 = b1s[16 * j + 8 + m2 + 1];
            hh[j][0] = pack2h(fmaxf(c1[2 * j][0] + be0, 0.f),
                              fmaxf(c1[2 * j][1] + be1, 0.f));
            hh[j][1] = pack2h(fmaxf(c1[2 * j][2] + be0, 0.f),
                              fmaxf(c1[2 * j][3] + be1, 0.f));
            hh[j][2] = pack2h(fmaxf(c1[2 * j + 1][0] + bo0, 0.f),
                              fmaxf(c1[2 * j + 1][1] + bo1, 0.f));
            hh[j][3] = pack2h(fmaxf(c1[2 * j + 1][2] + bo0, 0.f),
                              fmaxf(c1[2 * j + 1][3] + bo1, 0.f));
        }

        // ---- layer 2 in two n-halves, single-pass HMMA ----
        #pragma unroll
        for (int h = 0; h < 2; h++) {
            float c2[8][4];
            #pragma unroll
            for (int i = 0; i < 8; i++)
                c2[i][0] = c2[i][1] = c2[i][2] = c2[i][3] = 0.f;

            #pragma unroll
            for (int kk = 0; kk < 8; kk++) {
                #pragma unroll
                for (int i = 0; i < 4; i++) {
                    int nt2 = h * 4 + i;
                    uint32_t bAddr = sb + SM_W2H +
                        (uint32_t)((nt2 * 16 + brow) * RS + kk * 16 + bcol) * 2;
                    uint32_t bh[4];
                    ldsm4(bh, bAddr);
                    mma16816h(c2[2 * i],     hh[kk], bh[0], bh[1]);
                    mma16816h(c2[2 * i + 1], hh[kk], bh[2], bh[3]);
                }
            }

            #pragma unroll
            for (int nt = 0; nt < 8; nt++) {
                int col = (h * 8 + nt) * 8 + m2;
                float bb0 = b2s[col], bb1 = b2s[col + 1];
                if (val0)
                    *reinterpret_cast<float2*>(out + (size_t)r0 * D + col) =
                        make_float2(c2[nt][0] + bb0, c2[nt][1] + bb1);
                if (val1)
                    *reinterpret_cast<float2*>(out + (size_t)r1 * D + col) =
                        make_float2(c2[nt][2] + bb0, c2[nt][3] + bb1);
            }
        }
    }
}

// ---------------------------------------------------------------------------
// launch: setup (prep + eps-scaled init + x preload) -> scatter -> MLP
// ---------------------------------------------------------------------------
extern "C" void kernel_launch(void* const* d_in, const int* in_sizes, int n_in,
                              void* d_out, int out_size) {
    const float* x   = (const float*)d_in[0];
    const float* ea  = (const float*)d_in[1];
    const float* W1  = (const float*)d_in[2];
    const float* b1  = (const float*)d_in[3];
    const float* W2  = (const float*)d_in[4];
    const float* b2  = (const float*)d_in[5];
    const float* eps = (const float*)d_in[6];
    const int*   ei  = (const int*)d_in[7];

    int N = in_sizes[0] / D;
    int E = in_sizes[1] / D;

    int ninit4 = N * D / 4;
    int setup_blocks = 128 + (ninit4 + 255) / 256;
    setup_kernel<<<setup_blocks, 256>>>(W1, W2, x, eps, ninit4);

    long long scatter_threads = (long long)E * 32;
    scatter_kernel<<<(int)((scatter_threads + 255) / 256), 256>>>(x, ea, ei, E);

    cudaFuncSetAttribute(mlp_kernel,
                         cudaFuncAttributeMaxDynamicSharedMemorySize, SM_TOTAL);
    int ntiles = (N + 127) / 128;
    int grid = ntiles < 304 ? ntiles : 304;
    mlp_kernel<<<grid, 256, SM_TOTAL>>>(b1, b2, (float*)d_out, N, ntiles);
}

// round 17
// speedup vs baseline: 1.1380x; 1.0143x over previous
#include <cuda_runtime.h>
#include <cuda_fp16.h>
#include <cstdint>

static constexpr int D = 128;       // feature dim == hidden dim
static constexpr int MAXN = 100000;

// accumulator: initialized to (1+eps)*x by setup, then scatter adds messages
__device__ __align__(128) float g_acc[(size_t)MAXN * D];
// fp16 weights, transposed to [n][k] row-major, 128x128 each
__device__ __align__(16) __half g_w1h[16384];
__device__ __align__(16) __half g_w2h[16384];

// ---------------------------------------------------------------------------
// helpers
// ---------------------------------------------------------------------------
__device__ __forceinline__ uint32_t smem_to_u32(const void* p) {
    uint32_t a;
    asm("{ .reg .u64 t; cvta.to.shared.u64 t, %1; cvt.u32.u64 %0, t; }"
        : "=r"(a) : "l"(p));
    return a;
}
__device__ __forceinline__ void ldsm4(uint32_t r[4], uint32_t addr) {
    asm volatile("ldmatrix.sync.aligned.m8n8.x4.shared.b16 {%0,%1,%2,%3}, [%4];"
                 : "=r"(r[0]), "=r"(r[1]), "=r"(r[2]), "=r"(r[3]) : "r"(addr));
}
__device__ __forceinline__ void mma16816h(float c[4], const uint32_t a[4],
                                          uint32_t b0, uint32_t b1) {
    asm volatile("mma.sync.aligned.m16n8k16.row.col.f32.f16.f16.f32 "
                 "{%0,%1,%2,%3}, {%4,%5,%6,%7}, {%8,%9}, {%0,%1,%2,%3};"
                 : "+f"(c[0]), "+f"(c[1]), "+f"(c[2]), "+f"(c[3])
                 : "r"(a[0]), "r"(a[1]), "r"(a[2]), "r"(a[3]),
                   "r"(b0), "r"(b1));
}
// single packed fp16x2 convert
__device__ __forceinline__ uint32_t pack2h(float v0, float v1) {
    uint32_t hp;
    asm("cvt.rn.f16x2.f32 %0, %1, %2;" : "=r"(hp) : "f"(v1), "f"(v0));
    return hp;
}
// x row load pinned in L2 via cache-hint policy (evict_last)
__device__ __forceinline__ float4 ldg_keep(const float4* p, uint64_t pol) {
    float4 v;
    asm volatile("ld.global.nc.L2::cache_hint.v4.f32 {%0,%1,%2,%3}, [%4], %5;"
                 : "=f"(v.x), "=f"(v.y), "=f"(v.z), "=f"(v.w)
                 : "l"(p), "l"(pol));
    return v;
}

// ---------------------------------------------------------------------------
// setup: blocks [0,128) convert weights to fp16 [n][k]; rest: acc = (1+eps)*x
// x is read with evict_last => PRELOADS x into L2, pinned, for the scatter.
// ---------------------------------------------------------------------------
__global__ void setup_kernel(const float* __restrict__ W1,
                             const float* __restrict__ W2,
                             const float* __restrict__ x,
                             const float* __restrict__ eps, int ninit4) {
    int b = blockIdx.x, t = threadIdx.x;
    if (b < 128) {
        int idx = b * 256 + t;           // 0..32767
        int m = idx >> 14;
        int r = idx & 16383;
        int k = r >> 7, n = r & 127;
        float w = (m ? W2 : W1)[k * 128 + n];
        __half h = __float2half_rn(w);
        int e = n * 128 + k;
        if (m) g_w2h[e] = h;
        else   g_w1h[e] = h;
    } else {
        int i = (b - 128) * 256 + t;
        if (i < ninit4) {
            uint64_t pol;
            asm volatile("createpolicy.fractional.L2::evict_last.b64 %0, 1.0;"
                         : "=l"(pol));
            float s = 1.0f + *eps;
            float4 v = ldg_keep(reinterpret_cast<const float4*>(x) + i, pol);
            v.x *= s; v.y *= s; v.z *= s; v.w *= s;
            reinterpret_cast<float4*>(g_acc)[i] = v;
        }
    }
}

// ---------------------------------------------------------------------------
// scatter: EXACT R8/R14 form (proven): one warp per edge, red.v4 into g_acc;
// x pinned evict_last, ea streamed evict-first
// ---------------------------------------------------------------------------
__global__ void scatter_kernel(const float* __restrict__ x,
                               const float* __restrict__ ea,
                               const int* __restrict__ ei, int E) {
    int gtid = blockIdx.x * blockDim.x + threadIdx.x;
    int e = gtid >> 5;
    int lane = gtid & 31;
    if (e >= E) return;

    uint64_t pol;
    asm volatile("createpolicy.fractional.L2::evict_last.b64 %0, 1.0;"
                 : "=l"(pol));

    int u = ei[e];
    int v = ei[E + e];

    float4 a  = __ldcs(reinterpret_cast<const float4*>(ea + (size_t)e * D) + lane);
    float4 xu = ldg_keep(reinterpret_cast<const float4*>(x + (size_t)u * D) + lane, pol);
    float4 xv = ldg_keep(reinterpret_cast<const float4*>(x + (size_t)v * D) + lane, pol);

    float4 mu, mv;
    mu.x = fmaxf(xv.x + a.x, 0.0f); mu.y = fmaxf(xv.y + a.y, 0.0f);
    mu.z = fmaxf(xv.z + a.z, 0.0f); mu.w = fmaxf(xv.w + a.w, 0.0f);
    mv.x = fmaxf(xu.x + a.x, 0.0f); mv.y = fmaxf(xu.y + a.y, 0.0f);
    mv.z = fmaxf(xu.z + a.z, 0.0f); mv.w = fmaxf(xu.w + a.w, 0.0f);

    float* pu = g_acc + (size_t)u * D + lane * 4;
    float* pv = g_acc + (size_t)v * D + lane * 4;
    asm volatile("red.global.add.v4.f32 [%0], {%1,%2,%3,%4};"
                 :: "l"(pu), "f"(mu.x), "f"(mu.y), "f"(mu.z), "f"(mu.w) : "memory");
    asm volatile("red.global.add.v4.f32 [%0], {%1,%2,%3,%4};"
                 :: "l"(pv), "f"(mv.x), "f"(mv.y), "f"(mv.z), "f"(mv.w) : "memory");
}

// ---------------------------------------------------------------------------
// PERSISTENT fused MLP on HMMA fp16 — FULLY single-pass (A, hidden plain fp16)
// 256 threads / 8 warps per CTA, 2 CTAs/SM; W1h+W2h staged in smem ONCE;
// grid-stride over 128-row tiles; layer-1 A loads software-pipelined.
// ---------------------------------------------------------------------------
static constexpr int RS = 136;                        // row stride (fp16)
static constexpr int WT = 128 * RS * 2;               // 34816 B per tile
static constexpr int SM_W1H = 0;
static constexpr int SM_W2H = SM_W1H + WT;
static constexpr int SM_B1  = SM_W2H + WT;            // 69632
static constexpr int SM_B2  = SM_B1 + 512;
static constexpr int SM_TOTAL = SM_B2 + 512;          // 70656 B

__device__ __forceinline__ void copy_w256(char* smem, int dst,
                                          const __half* src, int tid) {
    const uint4* s = reinterpret_cast<const uint4*>(src);
    #pragma unroll
    for (int i = tid; i < 2048; i += 256) {
        int r = i >> 4, c8 = i & 15;
        *reinterpret_cast<uint4*>(smem + dst + (r * RS + c8 * 8) * 2) = s[i];
    }
}

__device__ __forceinline__ float2 ld2(const float* ap, bool valid, int k) {
    return valid ? *reinterpret_cast<const float2*>(ap + k)
                 : make_float2(0.f, 0.f);
}

__global__ void __launch_bounds__(256, 2)
mlp_kernel(const float* __restrict__ b1, const float* __restrict__ b2,
           float* __restrict__ out, int N, int ntiles) {
    extern __shared__ char smem[];
    uint32_t sb = smem_to_u32(smem);
    int tid = threadIdx.x;
    int wid = tid >> 5;
    int lane = tid & 31;

    copy_w256(smem, SM_W1H, g_w1h, tid);
    copy_w256(smem, SM_W2H, g_w2h, tid);
    if (tid < 128) {
        reinterpret_cast<float*>(smem + SM_B1)[tid] = b1[tid];
        reinterpret_cast<float*>(smem + SM_B2)[tid] = b2[tid];
    }
    __syncthreads();     // only barrier in the kernel

    int m2 = (lane & 3) * 2;
    int g  = lane >> 2;
    int brow = (lane & 7) + ((lane & 16) ? 8 : 0);
    int bcol = (lane & 8) ? 8 : 0;
    const float* b1s = reinterpret_cast<const float*>(smem + SM_B1);
    const float* b2s = reinterpret_cast<const float*>(smem + SM_B2);

    for (int tile = blockIdx.x; tile < ntiles; tile += gridDim.x) {
        int row0 = tile * 128;
        int r0 = row0 + wid * 16 + g;
        int r1 = r0 + 8;
        bool val0 = r0 < N, val1 = r1 < N;
        const float* a0p = g_acc + (size_t)r0 * D;
        const float* a1p = g_acc + (size_t)r1 * D;

        float c1[16][4];
        #pragma unroll
        for (int i = 0; i < 16; i++)
            c1[i][0] = c1[i][1] = c1[i][2] = c1[i][3] = 0.f;

        // ---- layer 1: software-pipelined A loads + single-pass HMMA ----
        float2 raw0 = ld2(a0p, val0, m2);
        float2 raw1 = ld2(a1p, val1, m2);
        float2 raw2 = ld2(a0p, val0, m2 + 8);
        float2 raw3 = ld2(a1p, val1, m2 + 8);
        #pragma unroll
        for (int kk = 0; kk < 8; kk++) {
            uint32_t ah[4];
            ah[0] = pack2h(raw0.x, raw0.y);
            ah[1] = pack2h(raw1.x, raw1.y);
            ah[2] = pack2h(raw2.x, raw2.y);
            ah[3] = pack2h(raw3.x, raw3.y);
            if (kk < 7) {
                int kn = (kk + 1) * 16 + m2;
                raw0 = ld2(a0p, val0, kn);
                raw1 = ld2(a1p, val1, kn);
                raw2 = ld2(a0p, val0, kn + 8);
                raw3 = ld2(a1p, val1, kn + 8);
            }
            #pragma unroll
            for (int nt2 = 0; nt2 < 8; nt2++) {
                uint32_t bAddr = sb + SM_W1H +
                    (uint32_t)((nt2 * 16 + brow) * RS + kk * 16 + bcol) * 2;
                uint32_t bh[4];
                ldsm4(bh, bAddr);
                mma16816h(c1[2 * nt2],     ah, bh[0], bh[1]);
                mma16816h(c1[2 * nt2 + 1], ah, bh[2], bh[3]);
            }
        }

        // ---- hidden = relu(c1 + b1), single fp16 fragment ----
        uint32_t hh[8][4];
        #pragma unroll
        for (int j = 0; j < 8; j++) {
            float be0 = b1s[16 * j + m2],     be1 = b1s[16 * j + m2 + 1];
            float bo0 = b1s[16 * j + 8 + m2], bo1 = b1s[16 * j + 8 + m2 + 1];
            hh[j][0] = pack2h(fmaxf(c1[2 * j][0] + be0, 0.f),
                              fmaxf(c1[2 * j][1] + be1, 0.f));
            hh[j][1] = pack2h(fmaxf(c1[2 * j][2] + be0, 0.f),
                              fmaxf(c1[2 * j][3] + be1, 0.f));
            hh[j][2] = pack2h(fmaxf(c1[2 * j + 1][0] + bo0, 0.f),
                              fmaxf(c1[2 * j + 1][1] + bo1, 0.f));
            hh[j][3] = pack2h(fmaxf(c1[2 * j + 1][2] + bo0, 0.f),
                              fmaxf(c1[2 * j + 1][3] + bo1, 0.f));
        }

        // ---- layer 2 in two n-halves, single-pass HMMA ----
        #pragma unroll
        for (int h = 0; h < 2; h++) {
            float c2[8][4];
            #pragma unroll
            for (int i = 0; i < 8; i++)
                c2[i][0] = c2[i][1] = c2[i][2] = c2[i][3] = 0.f;

            #pragma unroll
            for (int kk = 0; kk < 8; kk++) {
                #pragma unroll
                for (int i = 0; i < 4; i++) {
                    int nt2 = h * 4 + i;
                    uint32_t bAddr = sb + SM_W2H +
                        (uint32_t)((nt2 * 16 + brow) * RS + kk * 16 + bcol) * 2;
                    uint32_t bh[4];
                    ldsm4(bh, bAddr);
                    mma16816h(c2[2 * i],     hh[kk], bh[0], bh[1]);
                    mma16816h(c2[2 * i + 1], hh[kk], bh[2], bh[3]);
                }
            }

            #pragma unroll
            for (int nt = 0; nt < 8; nt++) {
                int col = (h * 8 + nt) * 8 + m2;
                float bb0 = b2s[col], bb1 = b2s[col + 1];
                if (val0)
                    *reinterpret_cast<float2*>(out + (size_t)r0 * D + col) =
                        make_float2(c2[nt][0] + bb0, c2[nt][1] + bb1);
                if (val1)
                    *reinterpret_cast<float2*>(out + (size_t)r1 * D + col) =
                        make_float2(c2[nt][2] + bb0, c2[nt][3] + bb1);
            }
        }
    }
}

// ---------------------------------------------------------------------------
// launch: setup (prep + eps-scaled init + x preload) -> scatter -> MLP
// ---------------------------------------------------------------------------
extern "C" void kernel_launch(void* const* d_in, const int* in_sizes, int n_in,
                              void* d_out, int out_size) {
    const float* x   = (const float*)d_in[0];
    const float* ea  = (const float*)d_in[1];
    const float* W1  = (const float*)d_in[2];
    const float* b1  = (const float*)d_in[3];
    const float* W2  = (const float*)d_in[4];
    const float* b2  = (const float*)d_in[5];
    const float* eps = (const float*)d_in[6];
    const int*   ei  = (const int*)d_in[7];

    int N = in_sizes[0] / D;
    int E = in_sizes[1] / D;

    int ninit4 = N * D / 4;
    int setup_blocks = 128 + (ninit4 + 255) / 256;
    setup_kernel<<<setup_blocks, 256>>>(W1, W2, x, eps, ninit4);

    long long scatter_threads = (long long)E * 32;
    scatter_kernel<<<(int)((scatter_threads + 255) / 256), 256>>>(x, ea, ei, E);

    cudaFuncSetAttribute(mlp_kernel,
                         cudaFuncAttributeMaxDynamicSharedMemorySize, SM_TOTAL);
    int ntiles = (N + 127) / 128;
    int grid = ntiles < 304 ? ntiles : 304;
    mlp_kernel<<<grid, 256, SM_TOTAL>>>(b1, b2, (float*)d_out, N, ntiles);
}